// round 7
// baseline (speedup 1.0000x reference)
#include <cuda_runtime.h>
#include <cstdint>

// out[m][d] = sum_k x[m][k] * W[k][d];  M=8192, K=4096, N=32, fp32.
//
// bf16x3 split GEMM on mma.sync (tcgen05 rejected by harness sm_103 target).
//   D += Ahi*Bhi + Ahi*Blo + Alo*Bhi  (fp32 accum), rel_err ~5e-6.
//
// R6: the R2/R4/R5 invariant (~43-47us gemm regardless of load shape, occ
// ~20%, nothing saturated) says the kernel is WARP-STARVED latency-bound.
// Fix concurrency, keep R4's best load shape:
//  - direct LDG.128 A (k-permuted fragments), no smem pipeline, no syncs.
//  - B fragment table in [step][c][h][r] order -> B LDG.128 = 4 full lines.
//  - KSPLIT=16 -> 1024 CTAs; __launch_bounds__(128,6) -> ~24 warps/SM.
//  - fused deterministic last-CTA reduction over 16 partials.

#define M_TOTAL 8192
#define K_TOTAL 4096
#define N_OUT   32
#define KSPLIT  16
#define KPER    (K_TOTAL / KSPLIT)     // 256
#define NIT     (KPER / 16)            // 16 k-steps per CTA
#define NSTEPG  (K_TOTAL / 16)         // 256 global k-steps
#define WARPS_CTA 4
#define THREADS  (WARPS_CTA * 32)
#define MB_ROWS  128
#define NMB      (M_TOTAL / MB_ROWS)   // 64
#define NCTA     (NMB * KSPLIT)        // 1024

__device__ float g_part[(size_t)KSPLIT * M_TOTAL * N_OUT];  // 16 MB (L2)
__device__ uint4 g_whi2[NSTEPG * 4 * 2 * 8];                // 256 KB
__device__ uint4 g_wlo2[NSTEPG * 4 * 2 * 8];                // 256 KB
__device__ int   g_cnt[NMB];

__device__ __forceinline__ void split2(float f0, float f1,
                                       uint32_t& hp, uint32_t& lp) {
    asm("cvt.rn.bf16x2.f32 %0, %1, %2;" : "=r"(hp) : "f"(f1), "f"(f0));
    float h0 = __uint_as_float(hp << 16);
    float h1 = __uint_as_float(hp & 0xffff0000u);
    float g0 = f0 - h0, g1 = f1 - h1;
    asm("cvt.rn.bf16x2.f32 %0, %1, %2;" : "=r"(lp) : "f"(g1), "f"(g0));
}

__device__ __forceinline__ void mma16816(float* d, const uint32_t* a,
                                         uint32_t b0, uint32_t b1) {
    asm volatile(
        "mma.sync.aligned.m16n8k16.row.col.f32.bf16.bf16.f32 "
        "{%0,%1,%2,%3}, {%4,%5,%6,%7}, {%8,%9}, {%0,%1,%2,%3};"
        : "+f"(d[0]), "+f"(d[1]), "+f"(d[2]), "+f"(d[3])
        : "r"(a[0]), "r"(a[1]), "r"(a[2]), "r"(a[3]), "r"(b0), "r"(b1));
}

// ---- W pre-split: idx = ((sg*4 + c)*2 + h)*8 + r  (16B uint4 units)
// word j = bf16x2( W[k][j*8+r], W[k+1][j*8+r] ), k = sg*16 + c*4 + h*2.
__global__ void __launch_bounds__(128)
wsplit_kernel(const float* __restrict__ w) {
    const int t = blockIdx.x * 128 + threadIdx.x;   // 16384
    const int r = t & 7, h = (t >> 3) & 1, c = (t >> 4) & 3, sg = t >> 6;
    const int k = sg * 16 + c * 4 + h * 2;
    uint32_t hi[4], lo[4];
    #pragma unroll
    for (int j = 0; j < 4; j++) {
        const int n = j * 8 + r;
        split2(w[(size_t)k * N_OUT + n], w[(size_t)(k + 1) * N_OUT + n],
               hi[j], lo[j]);
    }
    g_whi2[t] = make_uint4(hi[0], hi[1], hi[2], hi[3]);
    g_wlo2[t] = make_uint4(lo[0], lo[1], lo[2], lo[3]);
}

struct AF { float4 p[2][2]; };          // [mtile][row r / r+8]
struct BF { uint4 h0, h1, l0, l1; };

__global__ void __launch_bounds__(THREADS, 6)
gemm_hmma_kernel(const float* __restrict__ x, float* __restrict__ out) {
    const int tid  = threadIdx.x;
    const int wid  = tid >> 5, lane = tid & 31;
    const int mb   = blockIdx.x & (NMB - 1);
    const int kp   = blockIdx.x >> 6;
    const int m0   = mb * MB_ROWS + wid * 32;
    const int r    = lane >> 2;
    const int c    = lane & 3;

    const float* xa = x + (size_t)m0 * K_TOTAL + kp * KPER;
    const size_t bb = (size_t)(kp * NIT) * 64 + c * 16 + r;

    auto load_a = [&](int it, AF& a) {
        const int col = it * 16 + c * 4;
        #pragma unroll
        for (int i = 0; i < 2; i++) {
            a.p[i][0] = *(const float4*)(xa + (size_t)(i * 16 + r)     * K_TOTAL + col);
            a.p[i][1] = *(const float4*)(xa + (size_t)(i * 16 + r + 8) * K_TOTAL + col);
        }
    };
    auto load_b = [&](int it, BF& b) {
        const size_t u = bb + (size_t)it * 64;
        b.h0 = g_whi2[u]; b.h1 = g_whi2[u + 8];
        b.l0 = g_wlo2[u]; b.l1 = g_wlo2[u + 8];
    };

    float d[2][4][4];
    #pragma unroll
    for (int i = 0; i < 2; i++)
        #pragma unroll
        for (int j = 0; j < 4; j++)
            #pragma unroll
            for (int q = 0; q < 4; q++) d[i][j][q] = 0.f;

    auto step = [&](const AF& a, const BF& b) {
        uint32_t ahi[2][4], alo[2][4];
        #pragma unroll
        for (int i = 0; i < 2; i++) {
            split2(a.p[i][0].x, a.p[i][0].y, ahi[i][0], alo[i][0]);
            split2(a.p[i][1].x, a.p[i][1].y, ahi[i][1], alo[i][1]);
            split2(a.p[i][0].z, a.p[i][0].w, ahi[i][2], alo[i][2]);
            split2(a.p[i][1].z, a.p[i][1].w, ahi[i][3], alo[i][3]);
        }
        const uint32_t* h0 = &b.h0.x; const uint32_t* h1 = &b.h1.x;
        const uint32_t* l0 = &b.l0.x; const uint32_t* l1 = &b.l1.x;
        #pragma unroll
        for (int i = 0; i < 2; i++)
            #pragma unroll
            for (int j = 0; j < 4; j++) {
                mma16816(d[i][j], ahi[i], h0[j], h1[j]);
                mma16816(d[i][j], ahi[i], l0[j], l1[j]);
                mma16816(d[i][j], alo[i], h0[j], h1[j]);
            }
    };

    AF a0, a1; BF b0, b1;
    load_a(0, a0); load_b(0, b0);
    #pragma unroll 1
    for (int it = 0; it < NIT; it += 2) {
        const int n1 = (it + 1 < NIT) ? it + 1 : it;
        load_a(n1, a1); load_b(n1, b1);
        step(a0, b0);
        const int n2 = (it + 2 < NIT) ? it + 2 : it;
        load_a(n2, a0); load_b(n2, b0);
        step(a1, b1);
    }

    // ---- store partials ----
    float* base = g_part + ((size_t)kp * M_TOTAL + m0) * N_OUT;
    #pragma unroll
    for (int i = 0; i < 2; i++)
        #pragma unroll
        for (int j = 0; j < 4; j++) {
            const int col = j * 8 + c * 2;
            *(float2*)(base + (size_t)(i * 16 + r)     * N_OUT + col) =
                make_float2(d[i][j][0], d[i][j][1]);
            *(float2*)(base + (size_t)(i * 16 + r + 8) * N_OUT + col) =
                make_float2(d[i][j][2], d[i][j][3]);
        }

    // ---- deterministic fused reduction (last CTA per m-block) ----
    __shared__ int s_last;
    __threadfence();
    __syncthreads();
    if (tid == 0) {
        s_last = (atomicAdd(&g_cnt[mb], 1) == KSPLIT - 1);
        if (s_last) __threadfence();
    }
    __syncthreads();
    if (s_last) {
        const int nf4 = MB_ROWS * N_OUT / 4;              // 1024 float4
        const float4* sc = (const float4*)g_part;
        float4* dst = (float4*)out + (size_t)mb * nf4;
        #pragma unroll 1
        for (int q = tid; q < nf4; q += THREADS) {
            const size_t o = (size_t)mb * nf4 + q;
            float4 sv = make_float4(0.f, 0.f, 0.f, 0.f);
            #pragma unroll 1
            for (int g = 0; g < 2; g++) {           // two batches of 8 (MLP 8)
                float4 v[8];
                #pragma unroll
                for (int p = 0; p < 8; p++)
                    v[p] = sc[(size_t)(g * 8 + p) * (M_TOTAL * N_OUT / 4) + o];
                #pragma unroll
                for (int p = 0; p < 8; p++) {       // fixed order: deterministic
                    sv.x += v[p].x; sv.y += v[p].y;
                    sv.z += v[p].z; sv.w += v[p].w;
                }
            }
            dst[q] = sv;
        }
        if (tid == 0) g_cnt[mb] = 0;   // reset for graph replay
    }
}

extern "C" void kernel_launch(void* const* d_in, const int* in_sizes, int n_in,
                              void* d_out, int out_size) {
    const float* x = (const float*)d_in[0];   // [8192, 4096]
    const float* w = (const float*)d_in[1];   // [4096, 32]
    float* out = (float*)d_out;               // [8192, 32]

    wsplit_kernel<<<NSTEPG * 4 * 2 * 8 / 128, 128>>>(w);
    gemm_hmma_kernel<<<NCTA, THREADS>>>(x, out);
}